// round 9
// baseline (speedup 1.0000x reference)
#include <cuda_runtime.h>
#include <math.h>

// Problem constants
#define S_LEN  2048
#define BATCH  2
#define EMB    768
#define NHEAD  12
#define HD     64
#define NH     (BATCH*NHEAD)        // 24 flattened heads
#define M_ROWS (S_LEN*BATCH)        // 4096
#define OUT0   (S_LEN*BATCH*EMB)    // 3145728 floats (output tensor)

// ---------------- device scratch (static, allocation-free) ----------------
// g_Qh/g_Kh/g_Vh hold tf32-PREROUNDED values (bit pattern of cvt.rna.tf32).
__device__ float g_Qh[NH * S_LEN * HD];   // [head, s, d]
__device__ float g_Kh[NH * S_LEN * HD];
__device__ float g_Vh[NH * S_LEN * HD];
__device__ float g_ctx[M_ROWS * EMB];     // attn_output in [S,B,E] layout (full fp32)
__device__ float g_m[NH * S_LEN];         // per-row softmax max
__device__ float g_l[NH * S_LEN];         // per-row softmax sum

// ============================================================================
// portable (compute_103-safe) helpers
// tf32 m16n8k8 fragment layouts (PTX ISA):
//  A (16x8):  a0=(g, t)  a1=(g+8, t)  a2=(g, t+4)  a3=(g+8, t+4)   [g=lane>>2, t=lane&3]
//  B (8x8):   b0=(k=t, n=g)  b1=(k=t+4, n=g)
//  C (16x8):  c0=(g, 2t) c1=(g, 2t+1) c2=(g+8, 2t) c3=(g+8, 2t+1)
// ============================================================================
__device__ __forceinline__ unsigned sm_addr(const void* p) {
    unsigned a;
    asm("{ .reg .u64 t; cvta.to.shared.u64 t, %1; cvt.u32.u64 %0, t; }" : "=r"(a) : "l"(p));
    return a;
}
__device__ __forceinline__ unsigned f2tf(float x) {
    unsigned r;
    asm("cvt.rna.tf32.f32 %0, %1;" : "=r"(r) : "f"(x));
    return r;
}
__device__ __forceinline__ float f2tf_f(float x) { return __uint_as_float(f2tf(x)); }

__device__ __forceinline__ void mma_tf(float c[4], unsigned a0, unsigned a1,
                                       unsigned a2, unsigned a3,
                                       unsigned b0, unsigned b1) {
    asm volatile(
        "mma.sync.aligned.m16n8k8.row.col.f32.tf32.tf32.f32 "
        "{%0,%1,%2,%3}, {%4,%5,%6,%7}, {%8,%9}, {%0,%1,%2,%3};"
        : "+f"(c[0]), "+f"(c[1]), "+f"(c[2]), "+f"(c[3])
        : "r"(a0), "r"(a1), "r"(a2), "r"(a3), "r"(b0), "r"(b1));
}
__device__ __forceinline__ void cpa16(unsigned saddr, const void* gptr) {
    asm volatile("cp.async.cg.shared.global [%0], [%1], 16;" :: "r"(saddr), "l"(gptr));
}
#define CP_COMMIT()  asm volatile("cp.async.commit_group;")
#define CP_WAIT0()   asm volatile("cp.async.wait_group 0;")
#define CP_WAIT1()   asm volatile("cp.async.wait_group 1;")

// ============================================================================
// Projection GEMM core: C[128x128] = A[128x768] @ B[128x768]^T (both K-major).
// 8 warps (2x4): warp tile 64m x 32n; K-chunks of 32, cp.async double-buffered.
// Each landed chunk is converted to tf32 bits IN SMEM (one vector pass: 1024
// float4 slots per tile, A and B handled together), so the mma operand chains
// are pure LDS -> MMA (no F2FP in the critical path).
// ============================================================================
#define PLD 36
#define PROJ_SMEM (4 * 128 * PLD * 4)   // 73728 B

__device__ __forceinline__ void proj_core(const float* __restrict__ Ag,
                                          const float* __restrict__ Bg,
                                          float (&acc)[4][4][4], float* sh)
{
    float* Ab[2] = { sh,                 sh + 128 * PLD };
    float* Bb[2] = { sh + 2 * 128 * PLD, sh + 3 * 128 * PLD };
    const int tid = threadIdx.x;
    const int lane = tid & 31, wid = tid >> 5;
    const int g = lane >> 2, t = lane & 3;
    const int wy = wid >> 2, wx = wid & 3;

    auto stage = [&](int c, int bs) {
        #pragma unroll
        for (int i = 0; i < 4; i++) {
            int idx = tid + 256 * i;               // 0..1023 (float4 slots per tile)
            int row = idx >> 3, c4 = (idx & 7) * 4;
            cpa16(sm_addr(&Ab[bs][row * PLD + c4]), Ag + (size_t)row * EMB + c * 32 + c4);
            cpa16(sm_addr(&Bb[bs][row * PLD + c4]), Bg + (size_t)row * EMB + c * 32 + c4);
        }
        CP_COMMIT();
    };
    auto convert = [&](int bs) {                   // fp32 -> tf32 bits, in place
        #pragma unroll
        for (int i = 0; i < 4; i++) {              // 1024 slots; body does A and B
            int idx = tid + 256 * i;               // 0..1023
            int row = idx >> 3, c4 = (idx & 7) * 4;
            float4* pa = (float4*)&Ab[bs][row * PLD + c4];
            float4 va = *pa;
            va.x = f2tf_f(va.x); va.y = f2tf_f(va.y);
            va.z = f2tf_f(va.z); va.w = f2tf_f(va.w);
            *pa = va;
            float4* pb = (float4*)&Bb[bs][row * PLD + c4];
            float4 vb = *pb;
            vb.x = f2tf_f(vb.x); vb.y = f2tf_f(vb.y);
            vb.z = f2tf_f(vb.z); vb.w = f2tf_f(vb.w);
            *pb = vb;
        }
    };

    stage(0, 0);
    for (int c = 0; c < 24; c++) {
        __syncthreads();                 // prev compute finished before overwrite
        if (c + 1 < 24) { stage(c + 1, (c + 1) & 1); CP_WAIT1(); }
        else           { CP_WAIT0(); }
        __syncthreads();                 // chunk c landed, visible
        convert(c & 1);
        __syncthreads();                 // converted bits visible

        const float* Af = Ab[c & 1];
        const float* Bf = Bb[c & 1];
        #pragma unroll
        for (int ks = 0; ks < 4; ks++) {
            const int k0s = 8 * ks;
            unsigned a[4][4];
            #pragma unroll
            for (int mt = 0; mt < 4; mt++) {
                int ra = (64 * wy + 16 * mt + g) * PLD + k0s;
                a[mt][0] = __float_as_uint(Af[ra + t]);
                a[mt][1] = __float_as_uint(Af[ra + 8 * PLD + t]);
                a[mt][2] = __float_as_uint(Af[ra + t + 4]);
                a[mt][3] = __float_as_uint(Af[ra + 8 * PLD + t + 4]);
            }
            #pragma unroll
            for (int nt = 0; nt < 4; nt++) {
                int rb = (32 * wx + 8 * nt + g) * PLD + k0s;
                unsigned b0 = __float_as_uint(Bf[rb + t]);
                unsigned b1 = __float_as_uint(Bf[rb + t + 4]);
                #pragma unroll
                for (int mt = 0; mt < 4; mt++)
                    mma_tf(acc[mt][nt], a[mt][0], a[mt][1], a[mt][2], a[mt][3], b0, b1);
            }
        }
    }
}

// ============================================================================
// Kernel A: fused QKV projection.  grid (32, 6, 3); split-head output.
// Stores tf32-prerounded (acc+bias) so flash needs no conversions at all.
// ============================================================================
__global__ __launch_bounds__(256, 2) void qkv_gemm(
    const float* __restrict__ q, const float* __restrict__ k, const float* __restrict__ v,
    const float* __restrict__ WQ, const float* __restrict__ WK, const float* __restrict__ WV,
    const float* __restrict__ bQ, const float* __restrict__ bK, const float* __restrict__ bV)
{
    extern __shared__ float sh[];
    const int m0 = blockIdx.x * 128, n0 = blockIdx.y * 128, sel = blockIdx.z;
    const float* X    = (sel == 0) ? q  : (sel == 1) ? k  : v;
    const float* W    = (sel == 0) ? WQ : (sel == 1) ? WK : WV;
    const float* bias = (sel == 0) ? bQ : (sel == 1) ? bK : bV;
    float* dst        = (sel == 0) ? g_Qh : (sel == 1) ? g_Kh : g_Vh;

    float acc[4][4][4] = {};
    proj_core(X + (size_t)m0 * EMB, W + (size_t)n0 * EMB, acc, sh);

    const int tid = threadIdx.x, lane = tid & 31, wid = tid >> 5;
    const int g = lane >> 2, t = lane & 3;
    const int wy = wid >> 2, wx = wid & 3;
    #pragma unroll
    for (int mt = 0; mt < 4; mt++) {
        #pragma unroll
        for (int nt = 0; nt < 4; nt++) {
            int n = n0 + 32 * wx + 8 * nt + 2 * t;
            int h = n >> 6, d0 = n & 63;
            float bb0 = bias[n], bb1 = bias[n + 1];
            int row = m0 + 64 * wy + 16 * mt + g;
            {
                int s = row >> 1, bI = row & 1;
                float2 st = make_float2(f2tf_f(acc[mt][nt][0] + bb0),
                                        f2tf_f(acc[mt][nt][1] + bb1));
                *(float2*)&dst[((size_t)(bI * NHEAD + h) * S_LEN + s) * HD + d0] = st;
            }
            {
                int r2 = row + 8;
                int s = r2 >> 1, bI = r2 & 1;
                float2 st = make_float2(f2tf_f(acc[mt][nt][2] + bb0),
                                        f2tf_f(acc[mt][nt][3] + bb1));
                *(float2*)&dst[((size_t)(bI * NHEAD + h) * S_LEN + s) * HD + d0] = st;
            }
        }
    }
}

// ============================================================================
// Fused epilogue kernel: out-projection GEMM blocks + softmax-normalize blocks.
// Independent work overlapped in one launch (GEMM is latency-bound; norm is
// HBM-bound RMW of the 402MB weights region).
// grid.x = 192 gemm blocks [+ NORM_BLOCKS norm blocks when wraw != null].
// ============================================================================
#define NORM_BLOCKS 1536
// norm float4 count: NH*S*S/4 = 25165824 = 1536 blocks * 256 thr * 64 iters (exact)

__global__ __launch_bounds__(256, 2) void epilogue_fused(
    const float* __restrict__ W, const float* __restrict__ bias,
    float* __restrict__ out, float* __restrict__ wraw)
{
    const int bx = blockIdx.x;
    if (bx >= 192) {
        // ---- softmax normalize: w = exp(s - m[row]) / l[row] ----
        const long long nb = bx - 192;
        long long i4 = nb * 256 + threadIdx.x;
        const long long stride = (long long)NORM_BLOCKS * 256;
        #pragma unroll 4
        for (int j = 0; j < 64; j++) {
            long long row = i4 >> 9;              // / (S_LEN/4)
            float m = g_m[row];
            float inv = 1.f / g_l[row];
            float4* wv = (float4*)wraw + i4;
            float4 v = *wv;
            v.x = __expf(v.x - m) * inv;
            v.y = __expf(v.y - m) * inv;
            v.z = __expf(v.z - m) * inv;
            v.w = __expf(v.w - m) * inv;
            *wv = v;
            i4 += stride;
        }
        return;
    }

    // ---- out-projection: out = ctx @ W_O^T + b_O ----
    extern __shared__ float sh[];
    const int m0 = (bx & 31) * 128, n0 = (bx >> 5) * 128;

    float acc[4][4][4] = {};
    proj_core(g_ctx + (size_t)m0 * EMB, W + (size_t)n0 * EMB, acc, sh);

    const int tid = threadIdx.x, lane = tid & 31, wid = tid >> 5;
    const int g = lane >> 2, t = lane & 3;
    const int wy = wid >> 2, wx = wid & 3;
    #pragma unroll
    for (int mt = 0; mt < 4; mt++) {
        #pragma unroll
        for (int nt = 0; nt < 4; nt++) {
            int n = n0 + 32 * wx + 8 * nt + 2 * t;
            float bb0 = bias[n], bb1 = bias[n + 1];
            int row = m0 + 64 * wy + 16 * mt + g;
            *(float2*)&out[(size_t)row * EMB + n] =
                make_float2(acc[mt][nt][0] + bb0, acc[mt][nt][1] + bb1);
            *(float2*)&out[(size_t)(row + 8) * EMB + n] =
                make_float2(acc[mt][nt][2] + bb0, acc[mt][nt][3] + bb1);
        }
    }
}

// ============================================================================
// Kernel B: flash attention, tf32 mma.  grid (16, 24), 256 thr, 2 CTA/SM.
// Inputs arrive tf32-prerounded -> inner loops are pure LDS -> MMA.
// Warp w owns q-rows [16w,16w+16); full 64-k per warp (quad-local softmax).
// P round-trips through a per-warp smem tile (C-layout store, A-layout load).
// Pads: Q/K/P = 68 (bank 4g+t, conflict-free), V = 72 (bank 8t+g, conflict-free).
// ============================================================================
#define QPAD 68
#define KPAD 68
#define VPAD 72
#define PPAD 68
#define FLASH_SMEM ((128*QPAD + 64*KPAD + 64*VPAD + 128*PPAD) * 4)   // 105472 B

__global__ __launch_bounds__(256, 2) void flash_tc(float* __restrict__ wraw)
{
    extern __shared__ float sh[];
    float* Qs = sh;                          // [128][QPAD] tf32 bits
    float* Ks = Qs + 128 * QPAD;             // [64][KPAD]  tf32 bits
    float* Vs = Ks + 64 * KPAD;              // [64][VPAD]  tf32 bits
    float* Ps = Vs + 64 * VPAD;              // [128][PPAD] per-warp P tiles (tf32 bits)

    const int tid = threadIdx.x, lane = tid & 31, wid = tid >> 5;
    const int g = lane >> 2, t = lane & 3;
    const int hn = blockIdx.y;               // flattened head
    const int q0 = blockIdx.x * 128;

    const float* Qb = g_Qh + ((size_t)hn * S_LEN + q0) * HD;
    const float* Kb = g_Kh + (size_t)hn * S_LEN * HD;
    const float* Vb = g_Vh + (size_t)hn * S_LEN * HD;

    // preamble: stage Q, K0, V0 (already tf32 bits in gmem)
    #pragma unroll
    for (int i = 0; i < 8; i++) {
        int idx = tid + 256 * i; int row = idx >> 4, c4 = (idx & 15) * 4;
        cpa16(sm_addr(&Qs[row * QPAD + c4]), Qb + (size_t)row * HD + c4);
    }
    #pragma unroll
    for (int i = 0; i < 4; i++) {
        int idx = tid + 256 * i; int row = idx >> 4, c4 = (idx & 15) * 4;
        cpa16(sm_addr(&Ks[row * KPAD + c4]), Kb + (size_t)row * HD + c4);
        cpa16(sm_addr(&Vs[row * VPAD + c4]), Vb + (size_t)row * HD + c4);
    }
    CP_COMMIT();
    CP_WAIT0();

    float m0 = -INFINITY, m1 = -INFINITY, l0 = 0.f, l1 = 0.f;
    float oa[8][4] = {};
    const int qr = 16 * wid + g;             // warp-local base row (second = qr+8)
    float* Pw = Ps + wid * 16 * PPAD;        // per-warp P tile

    for (int kt = 0; kt < 32; kt++) {
        __syncthreads();                     // kt=0: preamble visible; kt>0: tail pair
        if (kt) { CP_WAIT0(); __syncthreads(); }   // K(kt), V(kt) landed + visible

        // ---- S = Q @ K^T / 8 ----
        float sa[8][4] = {};
        #pragma unroll
        for (int k8 = 0; k8 < 8; k8++) {
            int ra = qr * QPAD + 8 * k8;
            unsigned a0 = __float_as_uint(Qs[ra + t]);
            unsigned a1 = __float_as_uint(Qs[ra + 8 * QPAD + t]);
            unsigned a2 = __float_as_uint(Qs[ra + t + 4]);
            unsigned a3 = __float_as_uint(Qs[ra + 8 * QPAD + t + 4]);
            #pragma unroll
            for (int nt = 0; nt < 8; nt++) {
                int rb = (8 * nt + g) * KPAD + 8 * k8;
                mma_tf(sa[nt], a0, a1, a2, a3,
                       __float_as_uint(Ks[rb + t]),
                       __float_as_uint(Ks[rb + t + 4]));
            }
        }
        #pragma unroll
        for (int nt = 0; nt < 8; nt++) {
            sa[nt][0] *= 0.125f; sa[nt][1] *= 0.125f;
            sa[nt][2] *= 0.125f; sa[nt][3] *= 0.125f;
        }

        __syncthreads();                     // all warps done reading Ks
        if (kt < 31) {                       // prefetch K(kt+1) under softmax+PV
            #pragma unroll
            for (int i = 0; i < 4; i++) {
                int idx = tid + 256 * i; int row = idx >> 4, c4 = (idx & 15) * 4;
                cpa16(sm_addr(&Ks[row * KPAD + c4]),
                      Kb + (size_t)((kt + 1) * 64 + row) * HD + c4);
            }
            CP_COMMIT();
        }

        // ---- raw scores -> weights region (C layout: cols 2t,2t+1) ----
        if (wraw) {
            size_t rb0 = ((size_t)hn * S_LEN + (q0 + qr)) * S_LEN + (size_t)kt * 64 + 2 * t;
            #pragma unroll
            for (int nt = 0; nt < 8; nt++) {
                *(float2*)&wraw[rb0 + 8 * nt] = make_float2(sa[nt][0], sa[nt][1]);
                *(float2*)&wraw[rb0 + 8 * nt + 8 * (size_t)S_LEN] =
                    make_float2(sa[nt][2], sa[nt][3]);
            }
        }

        // ---- online softmax (row qr via c0/c1, row qr+8 via c2/c3) ----
        float lm0 = -INFINITY, lm1 = -INFINITY;
        #pragma unroll
        for (int nt = 0; nt < 8; nt++) {
            lm0 = fmaxf(lm0, fmaxf(sa[nt][0], sa[nt][1]));
            lm1 = fmaxf(lm1, fmaxf(sa[nt][2], sa[nt][3]));
        }
        lm0 = fmaxf(lm0, __shfl_xor_sync(0xffffffffu, lm0, 1));
        lm0 = fmaxf(lm0, __shfl_xor_sync(0xffffffffu, lm0, 2));
        lm1 = fmaxf(lm1, __shfl_xor_sync(0xffffffffu, lm1, 1));
        lm1 = fmaxf(lm1, __shfl_xor_sync(0xffffffffu, lm1, 2));
        float nm0 = fmaxf(m0, lm0), nm1 = fmaxf(m1, lm1);
        float ts0 = 0.f, ts1 = 0.f;
        #pragma unroll
        for (int nt = 0; nt < 8; nt++) {
            float p0 = __expf(sa[nt][0] - nm0);
            float p1 = __expf(sa[nt][1] - nm0);
            float p2 = __expf(sa[nt][2] - nm1);
            float p3 = __expf(sa[nt][3] - nm1);
            ts0 += p0 + p1; ts1 += p2 + p3;
            sa[nt][0] = f2tf_f(p0);          // tf32 bits, C layout
            sa[nt][1] = f2tf_f(p1);
            sa[nt][2] = f2tf_f(p2);
            sa[nt][3] = f2tf_f(p3);
        }
        ts0 += __shfl_xor_sync(0xffffffffu, ts0, 1);
        ts0 += __shfl_xor_sync(0xffffffffu, ts0, 2);
        ts1 += __shfl_xor_sync(0xffffffffu, ts1, 1);
        ts1 += __shfl_xor_sync(0xffffffffu, ts1, 2);
        float sc0 = __expf(m0 - nm0), sc1 = __expf(m1 - nm1);
        l0 = l0 * sc0 + ts0; l1 = l1 * sc1 + ts1;
        m0 = nm0; m1 = nm1;
        #pragma unroll
        for (int nt = 0; nt < 8; nt++) {
            oa[nt][0] *= sc0; oa[nt][1] *= sc0;
            oa[nt][2] *= sc1; oa[nt][3] *= sc1;
        }

        // ---- P: C-layout store to per-warp tile, A-layout reload ----
        #pragma unroll
        for (int nt = 0; nt < 8; nt++) {
            *(float2*)&Pw[g * PPAD + 8 * nt + 2 * t] =
                make_float2(sa[nt][0], sa[nt][1]);
            *(float2*)&Pw[(g + 8) * PPAD + 8 * nt + 2 * t] =
                make_float2(sa[nt][2], sa[nt][3]);
        }
        __syncwarp();

        // ---- O += P @ V ----
        #pragma unroll
        for (int k8 = 0; k8 < 8; k8++) {
            int pa = g * PPAD + 8 * k8;
            unsigned a0 = __float_as_uint(Pw[pa + t]);
            unsigned a1 = __float_as_uint(Pw[pa + 8 * PPAD + t]);
            unsigned a2 = __float_as_uint(Pw[pa + t + 4]);
            unsigned a3 = __float_as_uint(Pw[pa + 8 * PPAD + t + 4]);
            #pragma unroll
            for (int nt = 0; nt < 8; nt++) {
                int vb = (8 * k8 + t) * VPAD + 8 * nt + g;
                mma_tf(oa[nt], a0, a1, a2, a3,
                       __float_as_uint(Vs[vb]),
                       __float_as_uint(Vs[vb + 4 * VPAD]));
            }
        }
        __syncthreads();                     // all warps done reading Vs
        if (kt < 31) {                       // prefetch V(kt+1)
            #pragma unroll
            for (int i = 0; i < 4; i++) {
                int idx = tid + 256 * i; int row = idx >> 4, c4 = (idx & 15) * 4;
                cpa16(sm_addr(&Vs[row * VPAD + c4]),
                      Vb + (size_t)((kt + 1) * 64 + row) * HD + c4);
            }
            CP_COMMIT();
        }
    }

    // epilogue: normalize, scatter to [S,B,E], save (m,l)
    float inv0 = 1.f / l0, inv1 = 1.f / l1;
    const int r0 = q0 + qr, r1 = r0 + 8;
    const int bI = hn / NHEAD, hI = hn % NHEAD;
    #pragma unroll
    for (int nt = 0; nt < 8; nt++) {
        int d0 = 8 * nt + 2 * t;
        *(float2*)&g_ctx[((size_t)r0 * BATCH + bI) * EMB + hI * HD + d0] =
            make_float2(oa[nt][0] * inv0, oa[nt][1] * inv0);
        *(float2*)&g_ctx[((size_t)r1 * BATCH + bI) * EMB + hI * HD + d0] =
            make_float2(oa[nt][2] * inv1, oa[nt][3] * inv1);
    }
    if (t == 0) {
        g_m[hn * S_LEN + r0] = m0; g_m[hn * S_LEN + r1] = m1;
        g_l[hn * S_LEN + r0] = l0; g_l[hn * S_LEN + r1] = l1;
    }
}

// ============================================================================
// Fallback norm kernel (only used if wraw layout check fails epilogue path)
// ============================================================================
__global__ __launch_bounds__(256) void softmax_norm_kernel(float* __restrict__ w)
{
    size_t i4 = (size_t)blockIdx.x * blockDim.x + threadIdx.x;
    size_t row = i4 / (S_LEN / 4);
    float m = g_m[row];
    float inv = 1.f / g_l[row];
    float4* wv = (float4*)w + i4;
    float4 v = *wv;
    v.x = __expf(v.x - m) * inv;
    v.y = __expf(v.y - m) * inv;
    v.z = __expf(v.z - m) * inv;
    v.w = __expf(v.w - m) * inv;
    *wv = v;
}

// ============================================================================
extern "C" void kernel_launch(void* const* d_in, const int* in_sizes, int n_in,
                              void* d_out, int out_size)
{
    const float* q   = (const float*)d_in[0];
    const float* k   = (const float*)d_in[1];
    const float* v   = (const float*)d_in[2];
    const float* W_Q = (const float*)d_in[3];
    const float* W_K = (const float*)d_in[4];
    const float* W_V = (const float*)d_in[5];
    const float* b_Q = (const float*)d_in[6];
    const float* b_K = (const float*)d_in[7];
    const float* b_V = (const float*)d_in[8];
    const float* W_O = (const float*)d_in[9];
    const float* b_O = (const float*)d_in[10];
    float* out = (float*)d_out;

    const long long NW_LL = (long long)NH * S_LEN * S_LEN;  // 100663296
    const long long total = (long long)OUT0 + NW_LL;
    float* wraw = ((long long)out_size >= total) ? (out + OUT0) : nullptr;

    cudaFuncSetAttribute(qkv_gemm,
                         cudaFuncAttributeMaxDynamicSharedMemorySize, PROJ_SMEM);
    cudaFuncSetAttribute(epilogue_fused,
                         cudaFuncAttributeMaxDynamicSharedMemorySize, PROJ_SMEM);
    cudaFuncSetAttribute(flash_tc,
                         cudaFuncAttributeMaxDynamicSharedMemorySize, FLASH_SMEM);

    dim3 gQKV(M_ROWS / 128, EMB / 128, 3);   // 32 x 6 x 3
    qkv_gemm<<<gQKV, 256, PROJ_SMEM>>>(q, k, v, W_Q, W_K, W_V, b_Q, b_K, b_V);

    dim3 gB(S_LEN / 128, NH);                // 16 x 24
    flash_tc<<<gB, 256, FLASH_SMEM>>>(wraw);

    int epi_blocks = 192 + (wraw ? NORM_BLOCKS : 0);
    epilogue_fused<<<epi_blocks, 256, PROJ_SMEM>>>(W_O, b_O, out, wraw);
}